// round 11
// baseline (speedup 1.0000x reference)
#include <cuda_runtime.h>
#include <cuda_fp16.h>
#include <math.h>

#define BB    2
#define TT    2048
#define DIMM  1024
#define HH    16
#define DHH   64
#define MROWS 4096
#define QKVN  3072

// attention smem stride (halves)
#define ATSP  72
// gemm smem layout (halves): BK=64, A[128][72] + B[64][136], 3-stage ring
#define GASP2 72
#define GBSP  136
#define A_ST  (128 * GASP2)          // 9216
#define GSTG2 (A_ST + 64 * GBSP)     // 17920 halves = 35840 B / stage

// Scratch (allocation-free rule)
__device__ __half g_qkvh[(size_t)MROWS * QKVN];
__device__ __half g_y[(size_t)MROWS * DIMM];
__device__ __half g_xh[(size_t)MROWS * DIMM];
__device__ __half g_wqkvh[(size_t)DIMM * QKVN];
__device__ __half g_wouth[(size_t)DIMM * DIMM];
__device__ float2 g_rope[TT * 32];

// ---------------------------------------------------------------------------
// primitives
// ---------------------------------------------------------------------------
__device__ __forceinline__ void mma_f16(float* d, const unsigned* a, const unsigned* b) {
    asm volatile("mma.sync.aligned.m16n8k16.row.col.f32.f16.f16.f32 "
        "{%0,%1,%2,%3}, {%4,%5,%6,%7}, {%8,%9}, {%0,%1,%2,%3};"
        : "+f"(d[0]), "+f"(d[1]), "+f"(d[2]), "+f"(d[3])
        : "r"(a[0]), "r"(a[1]), "r"(a[2]), "r"(a[3]), "r"(b[0]), "r"(b[1]));
}
__device__ __forceinline__ void ldsm_x4(unsigned* r, unsigned addr) {
    asm volatile("ldmatrix.sync.aligned.m8n8.x4.shared.b16 {%0,%1,%2,%3}, [%4];"
        : "=r"(r[0]), "=r"(r[1]), "=r"(r[2]), "=r"(r[3]) : "r"(addr));
}
__device__ __forceinline__ void ldsm_x4t(unsigned* r, unsigned addr) {
    asm volatile("ldmatrix.sync.aligned.m8n8.x4.trans.shared.b16 {%0,%1,%2,%3}, [%4];"
        : "=r"(r[0]), "=r"(r[1]), "=r"(r[2]), "=r"(r[3]) : "r"(addr));
}
__device__ __forceinline__ unsigned smem_u32(const void* p) {
    return (unsigned)__cvta_generic_to_shared(p);
}
__device__ __forceinline__ unsigned packh2(float lo, float hi) {
    __half2 h = __float22half2_rn(make_float2(lo, hi));
    return *(unsigned*)&h;
}
__device__ __forceinline__ float ex2(float x) {
    float r;
    asm("ex2.approx.ftz.f32 %0, %1;" : "=f"(r) : "f"(x));
    return r;
}
#define CP_ASYNC16(dst, src) \
    asm volatile("cp.async.cg.shared.global [%0], [%1], 16;" :: "r"(dst), "l"(src))
#define CP_COMMIT() asm volatile("cp.async.commit_group;")
#define CP_WAIT1()  asm volatile("cp.async.wait_group 1;")
#define CP_WAIT0()  asm volatile("cp.async.wait_group 0;")

// ---------------------------------------------------------------------------
// Prologue (one launch): f32->f16 for x, W_qkv, W_out + rope cos/sin table
// ---------------------------------------------------------------------------
#define NX4   (MROWS * DIMM / 4)
#define NW14  (DIMM * QKVN / 4)
#define NW24  (DIMM * DIMM / 4)
#define NTOT4 (NX4 + NW14 + NW24)
__global__ void prologue_kernel(const float* __restrict__ x, __half* __restrict__ xh,
                                const float* __restrict__ w1, __half* __restrict__ w1h,
                                const float* __restrict__ w2, __half* __restrict__ w2h,
                                float2* __restrict__ tab)
{
    int i = blockIdx.x * blockDim.x + threadIdx.x;
    if (i < NTOT4) {
        const float* in; __half* out; int j;
        if (i < NX4)             { in = x;  out = xh;  j = i; }
        else if (i < NX4 + NW14) { in = w1; out = w1h; j = i - NX4; }
        else                     { in = w2; out = w2h; j = i - NX4 - NW14; }
        float4 v = ((const float4*)in)[j];
        __half2* o = (__half2*)out;
        o[2 * j]     = __float22half2_rn(make_float2(v.x, v.y));
        o[2 * j + 1] = __float22half2_rn(make_float2(v.z, v.w));
        return;
    }
    int idx = i - NTOT4;
    if (idx >= TT * 32) return;
    int d = idx & 31;
    int t = idx >> 5;

    double inv = 1.0;
    if (d & 1)  inv *= 0.74989420933245582;
    if (d & 2)  inv *= 0.56234132519034907;
    if (d & 4)  inv *= 0.31622776601683794;
    if (d & 8)  inv *= 0.1;
    if (d & 16) inv *= 0.01;

    double ang = (double)t * inv;
    double n = rint(ang * 0.15915494309189535);
    double r = fma(-n, 6.2831853071795862, ang);
    r = fma(-n, 2.4492935982947064e-16, r);

    float s, c;
    sincosf((float)r, &s, &c);
    tab[idx] = make_float2(c, s);
}

// ---------------------------------------------------------------------------
// fp16 GEMM, BK=64, 3-stage cp.async ring, templated epilogue:
//   MODE 0: C32 = A@B + bias (fp32)                         [out projection]
//   MODE 1: C16 = rope(A@B + bias) fp16; q scaled 0.125*log2e  [QKV]
// CTA 128x128, 8 warps (32x64). smem 3*35840 = 107520 B.
// ---------------------------------------------------------------------------
template <int MODE>
__global__ __launch_bounds__(256, 2)
void gemm_f16_kernel(const __half* __restrict__ A, const __half* __restrict__ Bm,
                     const float* __restrict__ bias, float* __restrict__ C32,
                     __half* __restrict__ C16, const float2* __restrict__ tab,
                     int M, int N, int K)
{
    extern __shared__ __half smg[];

    const int tid  = threadIdx.x;
    const int wid  = tid >> 5;
    const int lane = tid & 31;
    const int g    = lane >> 2;
    const int t    = lane & 3;
    const int wr   = wid >> 1;
    const int wc   = wid & 1;
    const int m0   = blockIdx.y * 128;
    const int n0   = blockIdx.x * 128;

    // staging: A 128x64 halves, B 64x128 halves; 4 16B chunks each per thread
    const int arow = tid >> 1, acol = (tid & 1) << 5;
    const int brow = tid >> 2, bcol = (tid & 3) << 5;
    const __half* pA = A + (size_t)(m0 + arow) * K + acol;
    const __half* pB = Bm + (size_t)brow * N + n0 + bcol;
    const unsigned base = smem_u32(smg);
    const unsigned dA = base + (unsigned)(arow * GASP2 + acol) * 2;
    const unsigned dB = base + (unsigned)(A_ST + brow * GBSP + bcol) * 2;

    const unsigned aC = base + (unsigned)((wr * 32 + (lane & 15)) * GASP2 + (lane >> 4) * 8) * 2;
    const unsigned bC = base + (unsigned)(A_ST + lane * GBSP + wc * 64) * 2;

    float acc[2][8][4];
#pragma unroll
    for (int mi = 0; mi < 2; mi++)
#pragma unroll
        for (int ni = 0; ni < 8; ni++)
#pragma unroll
            for (int j = 0; j < 4; j++) acc[mi][ni][j] = 0.f;

    const int ntiles = K >> 6;

    auto issue = [&](int kt) {
        const unsigned off = (unsigned)((kt % 3) * GSTG2) * 2;
#pragma unroll
        for (int c = 0; c < 4; c++)
            CP_ASYNC16(dA + off + c * 16, pA + kt * 64 + c * 8);
#pragma unroll
        for (int c = 0; c < 4; c++)
            CP_ASYNC16(dB + off + c * 16, pB + (size_t)kt * 64 * N + c * 8);
        CP_COMMIT();
    };

    issue(0);
    if (ntiles > 1) issue(1);

    for (int kt = 0; kt < ntiles; kt++) {
        if (kt + 1 < ntiles) { CP_WAIT1(); } else { CP_WAIT0(); }
        __syncthreads();
        if (kt + 2 < ntiles) issue(kt + 2);

        const unsigned soff = (unsigned)((kt % 3) * GSTG2) * 2;

#pragma unroll
        for (int h = 0; h < 2; h++) {
            unsigned af[2][2][4];   // [ks2][mi]
#pragma unroll
            for (int ks2 = 0; ks2 < 2; ks2++)
#pragma unroll
                for (int mi = 0; mi < 2; mi++)
                    ldsm_x4(af[ks2][mi],
                            aC + soff + (unsigned)(mi * 16 * GASP2 + h * 32 + ks2 * 16) * 2);

#pragma unroll
            for (int ni = 0; ni < 8; ni++) {
                unsigned bf[4];
                ldsm_x4t(bf, bC + soff + (unsigned)(h * 32 * GBSP + ni * 8) * 2);
#pragma unroll
                for (int mi = 0; mi < 2; mi++) {
                    mma_f16(acc[mi][ni], af[0][mi], bf);
                    mma_f16(acc[mi][ni], af[1][mi], bf + 2);
                }
            }
        }
        __syncthreads();
    }

    if (MODE == 0) {
#pragma unroll
        for (int mi = 0; mi < 2; mi++) {
            int r0 = m0 + wr * 32 + mi * 16 + g;
#pragma unroll
            for (int ni = 0; ni < 8; ni++) {
                int c = n0 + wc * 64 + ni * 8 + 2 * t;
                float2 bz = *(const float2*)&bias[c];
                *(float2*)&C32[(size_t)r0 * N + c] =
                    make_float2(acc[mi][ni][0] + bz.x, acc[mi][ni][1] + bz.y);
                *(float2*)&C32[(size_t)(r0 + 8) * N + c] =
                    make_float2(acc[mi][ni][2] + bz.x, acc[mi][ni][3] + bz.y);
            }
        }
    } else {
        const int nband = n0 + wc * 64;
        const bool is_v = (nband >= 2 * DIMM);
        // q scale folds softmax 1/8 AND log2(e): exp(s) == exp2(s*log2e)
        const float qs = (nband < DIMM) ? 0.125f * 1.44269504088896340736f : 1.0f;

        if (is_v) {
#pragma unroll
            for (int mi = 0; mi < 2; mi++) {
                int r0 = m0 + wr * 32 + mi * 16 + g;
#pragma unroll
                for (int ni = 0; ni < 8; ni++) {
                    int c = nband + ni * 8 + 2 * t;
                    float2 bz = *(const float2*)&bias[c];
                    *(unsigned*)&C16[(size_t)r0 * N + c] =
                        packh2(acc[mi][ni][0] + bz.x, acc[mi][ni][1] + bz.y);
                    *(unsigned*)&C16[(size_t)(r0 + 8) * N + c] =
                        packh2(acc[mi][ni][2] + bz.x, acc[mi][ni][3] + bz.y);
                }
            }
        } else {
#pragma unroll
            for (int mi = 0; mi < 2; mi++) {
                int r0 = m0 + wr * 32 + mi * 16 + g;
                int tr0 = r0 & (TT - 1);
                int tr1 = (r0 + 8) & (TT - 1);
#pragma unroll
                for (int ni = 0; ni < 4; ni++) {
                    int c  = nband + ni * 8 + 2 * t;
                    int d0 = (c & 63);
                    float2 bzA = *(const float2*)&bias[c];
                    float2 bzB = *(const float2*)&bias[c + 32];
                    float2 cs00 = tab[(tr0 << 5) | d0];
                    float2 cs01 = tab[(tr0 << 5) | (d0 + 1)];
                    float2 cs10 = tab[(tr1 << 5) | d0];
                    float2 cs11 = tab[(tr1 << 5) | (d0 + 1)];

                    float a0 = acc[mi][ni][0] + bzA.x,  a1 = acc[mi][ni][1] + bzA.y;
                    float b0 = acc[mi][ni + 4][0] + bzB.x, b1 = acc[mi][ni + 4][1] + bzB.y;
                    *(unsigned*)&C16[(size_t)r0 * N + c] =
                        packh2(qs * (a0 * cs00.x - b0 * cs00.y),
                               qs * (a1 * cs01.x - b1 * cs01.y));
                    *(unsigned*)&C16[(size_t)r0 * N + c + 32] =
                        packh2(qs * (a0 * cs00.y + b0 * cs00.x),
                               qs * (a1 * cs01.y + b1 * cs01.x));

                    a0 = acc[mi][ni][2] + bzA.x;  a1 = acc[mi][ni][3] + bzA.y;
                    b0 = acc[mi][ni + 4][2] + bzB.x; b1 = acc[mi][ni + 4][3] + bzB.y;
                    *(unsigned*)&C16[(size_t)(r0 + 8) * N + c] =
                        packh2(qs * (a0 * cs10.x - b0 * cs10.y),
                               qs * (a1 * cs11.x - b1 * cs11.y));
                    *(unsigned*)&C16[(size_t)(r0 + 8) * N + c + 32] =
                        packh2(qs * (a0 * cs10.y + b0 * cs10.x),
                               qs * (a1 * cs11.y + b1 * cs11.x));
                }
            }
        }
    }
}

// ---------------------------------------------------------------------------
// Flash attention (causal), fp16 mma, cp.async double-buffered K/V.
// Scores in log2-domain (q pre-scaled): exp -> single ex2.
// Row-sum l via ones-column trick: V padding col 64 = 1, cols 65..71 = 0;
// the 9th PV fragment accumulates l with the same alpha rescale as O.
// ---------------------------------------------------------------------------
__global__ __launch_bounds__(256, 2)
void attn_f16_kernel(const __half* __restrict__ qkvh, __half* __restrict__ y)
{
    extern __shared__ __half sma[];
    __half* Qs = sma;
    __half* Kd = Qs + 128 * ATSP;
    __half* Vd = Kd + 2 * 64 * ATSP;

    const int qb   = gridDim.x - 1 - blockIdx.x;
    const int h    = blockIdx.y;
    const int b    = blockIdx.z;
    const int tid  = threadIdx.x;
    const int wid  = tid >> 5;
    const int lane = tid & 31;
    const int g    = lane >> 2;
    const int t    = lane & 3;

    const __half* base = qkvh + (size_t)b * TT * QKVN + h * DHH;

    {
        const unsigned qd = smem_u32(Qs);
        int r0c = tid >> 3, c0 = (tid & 7) << 3;
#pragma unroll
        for (int l = 0; l < 4; l++) {
            int r = r0c + l * 32;
            CP_ASYNC16(qd + (unsigned)(r * ATSP + c0) * 2,
                       base + (size_t)(qb * 128 + r) * QKVN + c0);
        }
    }

    // ones-column init: V cols 64..71 := [1,0,0,0,0,0,0,0] (both buffers).
    // cp.async only ever writes cols 0..63, so this persists across kb.
    if (tid < 128) {
        uint4 pat = make_uint4(0x00003C00u, 0u, 0u, 0u);   // half 1.0, then zeros
        *(uint4*)(Vd + (size_t)tid * ATSP + 64) = pat;
    }

    const unsigned kdb = smem_u32(Kd), vdb = smem_u32(Vd);
    const int nkb = 2 * qb + 2;
    const int srr = tid >> 3, src = (tid & 7) << 3;

    auto issue_kv = [&](int kb, int buf) {
        const unsigned boff = (unsigned)(buf * 64 * ATSP) * 2;
#pragma unroll
        for (int l = 0; l < 2; l++) {
            int r = srr + l * 32;
            size_t gix = (size_t)(kb * 64 + r) * QKVN + src;
            unsigned doff = (unsigned)(r * ATSP + src) * 2;
            CP_ASYNC16(kdb + boff + doff, base + DIMM + gix);
            CP_ASYNC16(vdb + boff + doff, base + 2 * DIMM + gix);
        }
        CP_COMMIT();
    };

    issue_kv(0, 0);
    issue_kv(1, 1);

    const unsigned qfc = smem_u32(Qs) +
        (unsigned)((wid * 16 + (lane & 15)) * ATSP + (lane >> 4) * 8) * 2;
    const unsigned kfc = kdb +
        (unsigned)((((lane >> 4) << 3) + (lane & 7)) * ATSP + ((lane >> 3) & 1) * 8) * 2;
    const unsigned vfc = vdb + (unsigned)(lane * ATSP) * 2;

    float O[9][4];                      // [8] = ones-column (row sums)
#pragma unroll
    for (int nf = 0; nf < 9; nf++)
#pragma unroll
        for (int j = 0; j < 4; j++) O[nf][j] = 0.f;
    float m_lo = -1e30f, m_hi = -1e30f;

    const int rw0 = qb * 128 + wid * 16;

    for (int kb = 0; kb < nkb; kb++) {
        const int buf = kb & 1;
        if (kb + 1 < nkb) { CP_WAIT1(); } else { CP_WAIT0(); }
        __syncthreads();

        if (kb * 64 <= rw0 + 15) {
            const unsigned boff = (unsigned)(buf * 64 * ATSP) * 2;

            float S[8][4];
#pragma unroll
            for (int nf = 0; nf < 8; nf++)
#pragma unroll
                for (int j = 0; j < 4; j++) S[nf][j] = 0.f;

#pragma unroll
            for (int ks = 0; ks < 4; ks++) {
                unsigned aq[4];
                ldsm_x4(aq, qfc + (unsigned)(ks * 16) * 2);
#pragma unroll
                for (int nfp = 0; nfp < 4; nfp++) {
                    unsigned bk[4];
                    ldsm_x4(bk, kfc + boff +
                            (unsigned)(nfp * 16 * ATSP + ks * 16) * 2);
                    mma_f16(S[2 * nfp],     aq, bk);
                    mma_f16(S[2 * nfp + 1], aq, bk + 2);
                }
            }

            const int r0 = rw0 + g;
            const int r1 = r0 + 8;
            if (kb * 64 + 63 > rw0) {
#pragma unroll
                for (int nf = 0; nf < 8; nf++) {
                    int c0 = kb * 64 + nf * 8 + 2 * t;
                    if (c0     > r0) S[nf][0] = -1e30f;
                    if (c0 + 1 > r0) S[nf][1] = -1e30f;
                    if (c0     > r1) S[nf][2] = -1e30f;
                    if (c0 + 1 > r1) S[nf][3] = -1e30f;
                }
            }

            float mx0 = -1e30f, mx1 = -1e30f;
#pragma unroll
            for (int nf = 0; nf < 8; nf++) {
                mx0 = fmaxf(mx0, fmaxf(S[nf][0], S[nf][1]));
                mx1 = fmaxf(mx1, fmaxf(S[nf][2], S[nf][3]));
            }
            mx0 = fmaxf(mx0, __shfl_xor_sync(0xffffffffu, mx0, 1));
            mx0 = fmaxf(mx0, __shfl_xor_sync(0xffffffffu, mx0, 2));
            mx1 = fmaxf(mx1, __shfl_xor_sync(0xffffffffu, mx1, 1));
            mx1 = fmaxf(mx1, __shfl_xor_sync(0xffffffffu, mx1, 2));

            float mn0 = fmaxf(m_lo, mx0);
            float mn1 = fmaxf(m_hi, mx1);
            float al0 = ex2(m_lo - mn0);
            float al1 = ex2(m_hi - mn1);
            m_lo = mn0;  m_hi = mn1;
#pragma unroll
            for (int nf = 0; nf < 8; nf++) {
                S[nf][0] = ex2(S[nf][0] - mn0);
                S[nf][1] = ex2(S[nf][1] - mn0);
                S[nf][2] = ex2(S[nf][2] - mn1);
                S[nf][3] = ex2(S[nf][3] - mn1);
            }
#pragma unroll
            for (int nf = 0; nf < 9; nf++) {
                O[nf][0] *= al0; O[nf][1] *= al0;
                O[nf][2] *= al1; O[nf][3] *= al1;
            }

            unsigned aP[4][4];
#pragma unroll
            for (int ks = 0; ks < 4; ks++) {
                aP[ks][0] = packh2(S[2 * ks][0],     S[2 * ks][1]);
                aP[ks][1] = packh2(S[2 * ks][2],     S[2 * ks][3]);
                aP[ks][2] = packh2(S[2 * ks + 1][0], S[2 * ks + 1][1]);
                aP[ks][3] = packh2(S[2 * ks + 1][2], S[2 * ks + 1][3]);
            }

#pragma unroll
            for (int nf = 0; nf < 9; nf++) {
                unsigned vf[8];
                ldsm_x4t(vf,     vfc + boff + (unsigned)(nf * 8) * 2);
                ldsm_x4t(vf + 4, vfc + boff + (unsigned)(32 * ATSP + nf * 8) * 2);
#pragma unroll
                for (int ks = 0; ks < 4; ks++)
                    mma_f16(O[nf], aP[ks], vf + ((ks & 1) * 2) + ((ks >> 1) * 4));
            }
        }

        __syncthreads();
        if (kb + 2 < nkb) issue_kv(kb + 2, buf);
    }

    // recover row sums from the ones-column (quad lane t=0 holds col 64)
    const int qsrc = lane & 28;
    const float l_lo = __shfl_sync(0xffffffffu, O[8][0], qsrc);
    const float l_hi = __shfl_sync(0xffffffffu, O[8][2], qsrc);

    const float inv0 = 1.0f / l_lo;
    const float inv1 = 1.0f / l_hi;
    const int r0 = rw0 + g;
    const int r1 = r0 + 8;
    __half* yr0 = y + ((size_t)b * TT + r0) * DIMM + h * DHH;
    __half* yr1 = y + ((size_t)b * TT + r1) * DIMM + h * DHH;
#pragma unroll
    for (int nf = 0; nf < 8; nf++) {
        int c = nf * 8 + 2 * t;
        *(unsigned*)&yr0[c] = packh2(O[nf][0] * inv0, O[nf][1] * inv0);
        *(unsigned*)&yr1[c] = packh2(O[nf][2] * inv1, O[nf][3] * inv1);
    }
}

// ---------------------------------------------------------------------------
extern "C" void kernel_launch(void* const* d_in, const int* in_sizes, int n_in,
                              void* d_out, int out_size)
{
    const float* x     = (const float*)d_in[0];
    const float* W_qkv = (const float*)d_in[2];
    const float* b_qkv = (const float*)d_in[3];
    const float* W_out = (const float*)d_in[4];
    const float* b_out = (const float*)d_in[5];
    float* out = (float*)d_out;

    float2* rope;
    __half *qkvh, *y, *xh, *wqkvh, *wouth;
    cudaGetSymbolAddress((void**)&qkvh, g_qkvh);
    cudaGetSymbolAddress((void**)&y, g_y);
    cudaGetSymbolAddress((void**)&xh, g_xh);
    cudaGetSymbolAddress((void**)&wqkvh, g_wqkvh);
    cudaGetSymbolAddress((void**)&wouth, g_wouth);
    cudaGetSymbolAddress((void**)&rope, g_rope);

    const int gemm_smem = 3 * GSTG2 * 2;                 // 107520 B
    cudaFuncSetAttribute(gemm_f16_kernel<0>,
                         cudaFuncAttributeMaxDynamicSharedMemorySize, gemm_smem);
    cudaFuncSetAttribute(gemm_f16_kernel<1>,
                         cudaFuncAttributeMaxDynamicSharedMemorySize, gemm_smem);
    const int attn_smem = (128 + 4 * 64) * ATSP * 2;     // 55296 B
    cudaFuncSetAttribute(attn_f16_kernel,
                         cudaFuncAttributeMaxDynamicSharedMemorySize, attn_smem);

    // 0) fp16 conversions + rope table (one launch)
    prologue_kernel<<<(NTOT4 + TT * 32 + 255) / 256, 256>>>(
        x, xh, W_qkv, wqkvh, W_out, wouth, rope);

    // 1) qkvh = rope(xh @ wqkvh + b_qkv), q pre-scaled by 0.125*log2e
    gemm_f16_kernel<1><<<dim3(QKVN / 128, MROWS / 128), 256, gemm_smem>>>(
        xh, wqkvh, b_qkv, nullptr, qkvh, rope, MROWS, QKVN, DIMM);

    // 2) causal flash attention -> y (fp16)
    attn_f16_kernel<<<dim3(TT / 128, HH, BB), 256, attn_smem>>>(qkvh, y);

    // 3) out = y @ wouth + b_out (fp32)
    gemm_f16_kernel<0><<<dim3(DIMM / 128, MROWS / 128), 256, gemm_smem>>>(
        y, wouth, b_out, out, nullptr, nullptr, MROWS, DIMM, DIMM);
}

// round 14
// speedup vs baseline: 1.1508x; 1.1508x over previous
#include <cuda_runtime.h>
#include <cuda_fp16.h>
#include <math.h>

#define BB    2
#define TT    2048
#define DIMM  1024
#define HH    16
#define DHH   64
#define MROWS 4096
#define QKVN  3072

// attention smem stride (halves)
#define ATSP  72
// gemm smem strides (halves) — R10 proven config: BK=32
#define GASP  40
#define GBSP  136
#define GSTGH (128 * GASP + 32 * GBSP)

// Scratch (allocation-free rule)
__device__ __half g_qkvh[(size_t)MROWS * QKVN];
__device__ __half g_y[(size_t)MROWS * DIMM];
__device__ __half g_xh[(size_t)MROWS * DIMM];
__device__ __half g_wqkvh[(size_t)DIMM * QKVN];
__device__ __half g_wouth[(size_t)DIMM * DIMM];
__device__ float2 g_rope[TT * 32];

// ---------------------------------------------------------------------------
// primitives
// ---------------------------------------------------------------------------
__device__ __forceinline__ void mma_f16(float* d, const unsigned* a, const unsigned* b) {
    asm volatile("mma.sync.aligned.m16n8k16.row.col.f32.f16.f16.f32 "
        "{%0,%1,%2,%3}, {%4,%5,%6,%7}, {%8,%9}, {%0,%1,%2,%3};"
        : "+f"(d[0]), "+f"(d[1]), "+f"(d[2]), "+f"(d[3])
        : "r"(a[0]), "r"(a[1]), "r"(a[2]), "r"(a[3]), "r"(b[0]), "r"(b[1]));
}
__device__ __forceinline__ void ldsm_x4(unsigned* r, unsigned addr) {
    asm volatile("ldmatrix.sync.aligned.m8n8.x4.shared.b16 {%0,%1,%2,%3}, [%4];"
        : "=r"(r[0]), "=r"(r[1]), "=r"(r[2]), "=r"(r[3]) : "r"(addr));
}
__device__ __forceinline__ void ldsm_x4t(unsigned* r, unsigned addr) {
    asm volatile("ldmatrix.sync.aligned.m8n8.x4.trans.shared.b16 {%0,%1,%2,%3}, [%4];"
        : "=r"(r[0]), "=r"(r[1]), "=r"(r[2]), "=r"(r[3]) : "r"(addr));
}
__device__ __forceinline__ unsigned smem_u32(const void* p) {
    return (unsigned)__cvta_generic_to_shared(p);
}
__device__ __forceinline__ unsigned packh2(float lo, float hi) {
    __half2 h = __float22half2_rn(make_float2(lo, hi));
    return *(unsigned*)&h;
}
__device__ __forceinline__ float ex2(float x) {
    float r;
    asm("ex2.approx.ftz.f32 %0, %1;" : "=f"(r) : "f"(x));
    return r;
}
#define CP_ASYNC16(dst, src) \
    asm volatile("cp.async.cg.shared.global [%0], [%1], 16;" :: "r"(dst), "l"(src))
#define CP_COMMIT() asm volatile("cp.async.commit_group;")
#define CP_WAIT1()  asm volatile("cp.async.wait_group 1;")
#define CP_WAIT0()  asm volatile("cp.async.wait_group 0;")

// ---------------------------------------------------------------------------
// Prologue (one launch): f32->f16 for x, W_qkv, W_out + rope cos/sin table
// ---------------------------------------------------------------------------
#define NX4   (MROWS * DIMM / 4)
#define NW14  (DIMM * QKVN / 4)
#define NW24  (DIMM * DIMM / 4)
#define NTOT4 (NX4 + NW14 + NW24)
__global__ void prologue_kernel(const float* __restrict__ x, __half* __restrict__ xh,
                                const float* __restrict__ w1, __half* __restrict__ w1h,
                                const float* __restrict__ w2, __half* __restrict__ w2h,
                                float2* __restrict__ tab)
{
    int i = blockIdx.x * blockDim.x + threadIdx.x;
    if (i < NTOT4) {
        const float* in; __half* out; int j;
        if (i < NX4)             { in = x;  out = xh;  j = i; }
        else if (i < NX4 + NW14) { in = w1; out = w1h; j = i - NX4; }
        else                     { in = w2; out = w2h; j = i - NX4 - NW14; }
        float4 v = ((const float4*)in)[j];
        __half2* o = (__half2*)out;
        o[2 * j]     = __float22half2_rn(make_float2(v.x, v.y));
        o[2 * j + 1] = __float22half2_rn(make_float2(v.z, v.w));
        return;
    }
    int idx = i - NTOT4;
    if (idx >= TT * 32) return;
    int d = idx & 31;
    int t = idx >> 5;

    double inv = 1.0;
    if (d & 1)  inv *= 0.74989420933245582;
    if (d & 2)  inv *= 0.56234132519034907;
    if (d & 4)  inv *= 0.31622776601683794;
    if (d & 8)  inv *= 0.1;
    if (d & 16) inv *= 0.01;

    double ang = (double)t * inv;
    double n = rint(ang * 0.15915494309189535);
    double r = fma(-n, 6.2831853071795862, ang);
    r = fma(-n, 2.4492935982947064e-16, r);

    float s, c;
    sincosf((float)r, &s, &c);
    tab[idx] = make_float2(c, s);
}

// ---------------------------------------------------------------------------
// fp16 GEMM (R10-proven mainloop): BK=32, 3-stage cp.async ring, one sync.
//   MODE 0: C32 = A@B + bias (fp32)                             [out proj]
//   MODE 1: C16 = rope(A@B + bias) fp16; q scaled 0.125*log2e   [QKV]
// CTA 128x128, 8 warps (32x64).
// ---------------------------------------------------------------------------
template <int MODE>
__global__ __launch_bounds__(256, 2)
void gemm_f16_kernel(const __half* __restrict__ A, const __half* __restrict__ Bm,
                     const float* __restrict__ bias, float* __restrict__ C32,
                     __half* __restrict__ C16, const float2* __restrict__ tab,
                     int M, int N, int K)
{
    extern __shared__ __half smg[];

    const int tid  = threadIdx.x;
    const int wid  = tid >> 5;
    const int lane = tid & 31;
    const int g    = lane >> 2;
    const int t    = lane & 3;
    const int wr   = wid >> 1;
    const int wc   = wid & 1;
    const int m0   = blockIdx.y * 128;
    const int n0   = blockIdx.x * 128;

    const int arow = tid >> 2, acol = (tid & 3) << 3;
    const int brow = tid >> 4, bcol = (tid & 15) << 3;
    const __half* pA0 = A + (size_t)(m0 + arow) * K + acol;
    const __half* pA1 = pA0 + (size_t)64 * K;
    const __half* pB0 = Bm + (size_t)brow * N + n0 + bcol;
    const __half* pB1 = pB0 + (size_t)16 * N;
    const unsigned base = smem_u32(smg);
    const unsigned dA0 = base + (unsigned)(arow * GASP + acol) * 2;
    const unsigned dA1 = dA0 + 64 * GASP * 2;
    const unsigned dB0 = base + (unsigned)(128 * GASP + brow * GBSP + bcol) * 2;
    const unsigned dB1 = dB0 + 16 * GBSP * 2;

    const unsigned aC = base + (unsigned)((wr * 32 + (lane & 15)) * GASP + (lane >> 4) * 8) * 2;
    const unsigned bC = base + (unsigned)(128 * GASP + lane * GBSP + wc * 64) * 2;

    float acc[2][8][4];
#pragma unroll
    for (int mi = 0; mi < 2; mi++)
#pragma unroll
        for (int ni = 0; ni < 8; ni++)
#pragma unroll
            for (int j = 0; j < 4; j++) acc[mi][ni][j] = 0.f;

    const int ntiles = K >> 5;

    auto issue = [&](int kt) {
        const unsigned off = (unsigned)((kt % 3) * GSTGH) * 2;
        CP_ASYNC16(dA0 + off, pA0 + kt * 32);
        CP_ASYNC16(dA1 + off, pA1 + kt * 32);
        CP_ASYNC16(dB0 + off, pB0 + (size_t)kt * 32 * N);
        CP_ASYNC16(dB1 + off, pB1 + (size_t)kt * 32 * N);
        CP_COMMIT();
    };

    issue(0);
    if (ntiles > 1) issue(1);

    for (int kt = 0; kt < ntiles; kt++) {
        if (kt + 1 < ntiles) { CP_WAIT1(); } else { CP_WAIT0(); }
        __syncthreads();
        if (kt + 2 < ntiles) issue(kt + 2);

        const unsigned soff = (unsigned)((kt % 3) * GSTGH) * 2;

        unsigned af[2][2][4];
#pragma unroll
        for (int ks = 0; ks < 2; ks++)
#pragma unroll
            for (int mi = 0; mi < 2; mi++)
                ldsm_x4(af[ks][mi], aC + soff + (unsigned)(mi * 16 * GASP + ks * 16) * 2);

#pragma unroll
        for (int ni = 0; ni < 8; ni++) {
            unsigned bf[4];
            ldsm_x4t(bf, bC + soff + (unsigned)(ni * 8) * 2);
#pragma unroll
            for (int mi = 0; mi < 2; mi++) {
                mma_f16(acc[mi][ni], af[0][mi], bf);
                mma_f16(acc[mi][ni], af[1][mi], bf + 2);
            }
        }
    }

    if (MODE == 0) {
#pragma unroll
        for (int mi = 0; mi < 2; mi++) {
            int r0 = m0 + wr * 32 + mi * 16 + g;
#pragma unroll
            for (int ni = 0; ni < 8; ni++) {
                int c = n0 + wc * 64 + ni * 8 + 2 * t;
                float2 bz = *(const float2*)&bias[c];
                *(float2*)&C32[(size_t)r0 * N + c] =
                    make_float2(acc[mi][ni][0] + bz.x, acc[mi][ni][1] + bz.y);
                *(float2*)&C32[(size_t)(r0 + 8) * N + c] =
                    make_float2(acc[mi][ni][2] + bz.x, acc[mi][ni][3] + bz.y);
            }
        }
    } else {
        const int nband = n0 + wc * 64;
        const bool is_v = (nband >= 2 * DIMM);
        // q scale folds softmax 1/8 AND log2(e): exp(s) == exp2(s*log2e)
        const float qs = (nband < DIMM) ? 0.125f * 1.44269504088896340736f : 1.0f;

        if (is_v) {
#pragma unroll
            for (int mi = 0; mi < 2; mi++) {
                int r0 = m0 + wr * 32 + mi * 16 + g;
#pragma unroll
                for (int ni = 0; ni < 8; ni++) {
                    int c = nband + ni * 8 + 2 * t;
                    float2 bz = *(const float2*)&bias[c];
                    *(unsigned*)&C16[(size_t)r0 * N + c] =
                        packh2(acc[mi][ni][0] + bz.x, acc[mi][ni][1] + bz.y);
                    *(unsigned*)&C16[(size_t)(r0 + 8) * N + c] =
                        packh2(acc[mi][ni][2] + bz.x, acc[mi][ni][3] + bz.y);
                }
            }
        } else {
#pragma unroll
            for (int mi = 0; mi < 2; mi++) {
                int r0 = m0 + wr * 32 + mi * 16 + g;
                int tr0 = r0 & (TT - 1);
                int tr1 = (r0 + 8) & (TT - 1);
#pragma unroll
                for (int ni = 0; ni < 4; ni++) {
                    int c  = nband + ni * 8 + 2 * t;
                    int d0 = (c & 63);
                    float2 bzA = *(const float2*)&bias[c];
                    float2 bzB = *(const float2*)&bias[c + 32];
                    float2 cs00 = tab[(tr0 << 5) | d0];
                    float2 cs01 = tab[(tr0 << 5) | (d0 + 1)];
                    float2 cs10 = tab[(tr1 << 5) | d0];
                    float2 cs11 = tab[(tr1 << 5) | (d0 + 1)];

                    float a0 = acc[mi][ni][0] + bzA.x,  a1 = acc[mi][ni][1] + bzA.y;
                    float b0 = acc[mi][ni + 4][0] + bzB.x, b1 = acc[mi][ni + 4][1] + bzB.y;
                    *(unsigned*)&C16[(size_t)r0 * N + c] =
                        packh2(qs * (a0 * cs00.x - b0 * cs00.y),
                               qs * (a1 * cs01.x - b1 * cs01.y));
                    *(unsigned*)&C16[(size_t)r0 * N + c + 32] =
                        packh2(qs * (a0 * cs00.y + b0 * cs00.x),
                               qs * (a1 * cs01.y + b1 * cs01.x));

                    a0 = acc[mi][ni][2] + bzA.x;  a1 = acc[mi][ni][3] + bzA.y;
                    b0 = acc[mi][ni + 4][2] + bzB.x; b1 = acc[mi][ni + 4][3] + bzB.y;
                    *(unsigned*)&C16[(size_t)(r0 + 8) * N + c] =
                        packh2(qs * (a0 * cs10.x - b0 * cs10.y),
                               qs * (a1 * cs11.x - b1 * cs11.y));
                    *(unsigned*)&C16[(size_t)(r0 + 8) * N + c + 32] =
                        packh2(qs * (a0 * cs10.y + b0 * cs10.x),
                               qs * (a1 * cs11.y + b1 * cs11.x));
                }
            }
        }
    }
}

// ---------------------------------------------------------------------------
// Flash attention (causal), fp16 mma, cp.async double-buffered K/V.
// log2-domain scores (q pre-scaled) -> single ex2; row-sum l via ones-column.
// ---------------------------------------------------------------------------
__global__ __launch_bounds__(256, 2)
void attn_f16_kernel(const __half* __restrict__ qkvh, __half* __restrict__ y)
{
    extern __shared__ __half sma[];
    __half* Qs = sma;
    __half* Kd = Qs + 128 * ATSP;
    __half* Vd = Kd + 2 * 64 * ATSP;

    const int qb   = gridDim.x - 1 - blockIdx.x;
    const int h    = blockIdx.y;
    const int b    = blockIdx.z;
    const int tid  = threadIdx.x;
    const int wid  = tid >> 5;
    const int lane = tid & 31;
    const int g    = lane >> 2;
    const int t    = lane & 3;

    const __half* base = qkvh + (size_t)b * TT * QKVN + h * DHH;

    {
        const unsigned qd = smem_u32(Qs);
        int r0c = tid >> 3, c0 = (tid & 7) << 3;
#pragma unroll
        for (int l = 0; l < 4; l++) {
            int r = r0c + l * 32;
            CP_ASYNC16(qd + (unsigned)(r * ATSP + c0) * 2,
                       base + (size_t)(qb * 128 + r) * QKVN + c0);
        }
    }

    // ones-column init: V cols 64..71 := [1,0,...]; cp.async never touches them
    if (tid < 128) {
        uint4 pat = make_uint4(0x00003C00u, 0u, 0u, 0u);
        *(uint4*)(Vd + (size_t)tid * ATSP + 64) = pat;
    }

    const unsigned kdb = smem_u32(Kd), vdb = smem_u32(Vd);
    const int nkb = 2 * qb + 2;
    const int srr = tid >> 3, src = (tid & 7) << 3;

    auto issue_kv = [&](int kb, int buf) {
        const unsigned boff = (unsigned)(buf * 64 * ATSP) * 2;
#pragma unroll
        for (int l = 0; l < 2; l++) {
            int r = srr + l * 32;
            size_t gix = (size_t)(kb * 64 + r) * QKVN + src;
            unsigned doff = (unsigned)(r * ATSP + src) * 2;
            CP_ASYNC16(kdb + boff + doff, base + DIMM + gix);
            CP_ASYNC16(vdb + boff + doff, base + 2 * DIMM + gix);
        }
        CP_COMMIT();
    };

    issue_kv(0, 0);
    issue_kv(1, 1);

    const unsigned qfc = smem_u32(Qs) +
        (unsigned)((wid * 16 + (lane & 15)) * ATSP + (lane >> 4) * 8) * 2;
    const unsigned kfc = kdb +
        (unsigned)((((lane >> 4) << 3) + (lane & 7)) * ATSP + ((lane >> 3) & 1) * 8) * 2;
    const unsigned vfc = vdb + (unsigned)(lane * ATSP) * 2;

    float O[9][4];                      // [8] = ones-column (row sums)
#pragma unroll
    for (int nf = 0; nf < 9; nf++)
#pragma unroll
        for (int j = 0; j < 4; j++) O[nf][j] = 0.f;
    float m_lo = -1e30f, m_hi = -1e30f;

    const int rw0 = qb * 128 + wid * 16;

    for (int kb = 0; kb < nkb; kb++) {
        const int buf = kb & 1;
        if (kb + 1 < nkb) { CP_WAIT1(); } else { CP_WAIT0(); }
        __syncthreads();

        if (kb * 64 <= rw0 + 15) {
            const unsigned boff = (unsigned)(buf * 64 * ATSP) * 2;

            float S[8][4];
#pragma unroll
            for (int nf = 0; nf < 8; nf++)
#pragma unroll
                for (int j = 0; j < 4; j++) S[nf][j] = 0.f;

#pragma unroll
            for (int ks = 0; ks < 4; ks++) {
                unsigned aq[4];
                ldsm_x4(aq, qfc + (unsigned)(ks * 16) * 2);
#pragma unroll
                for (int nfp = 0; nfp < 4; nfp++) {
                    unsigned bk[4];
                    ldsm_x4(bk, kfc + boff +
                            (unsigned)(nfp * 16 * ATSP + ks * 16) * 2);
                    mma_f16(S[2 * nfp],     aq, bk);
                    mma_f16(S[2 * nfp + 1], aq, bk + 2);
                }
            }

            const int r0 = rw0 + g;
            const int r1 = r0 + 8;
            if (kb * 64 + 63 > rw0) {
#pragma unroll
                for (int nf = 0; nf < 8; nf++) {
                    int c0 = kb * 64 + nf * 8 + 2 * t;
                    if (c0     > r0) S[nf][0] = -1e30f;
                    if (c0 + 1 > r0) S[nf][1] = -1e30f;
                    if (c0     > r1) S[nf][2] = -1e30f;
                    if (c0 + 1 > r1) S[nf][3] = -1e30f;
                }
            }

            float mx0 = -1e30f, mx1 = -1e30f;
#pragma unroll
            for (int nf = 0; nf < 8; nf++) {
                mx0 = fmaxf(mx0, fmaxf(S[nf][0], S[nf][1]));
                mx1 = fmaxf(mx1, fmaxf(S[nf][2], S[nf][3]));
            }
            mx0 = fmaxf(mx0, __shfl_xor_sync(0xffffffffu, mx0, 1));
            mx0 = fmaxf(mx0, __shfl_xor_sync(0xffffffffu, mx0, 2));
            mx1 = fmaxf(mx1, __shfl_xor_sync(0xffffffffu, mx1, 1));
            mx1 = fmaxf(mx1, __shfl_xor_sync(0xffffffffu, mx1, 2));

            float mn0 = fmaxf(m_lo, mx0);
            float mn1 = fmaxf(m_hi, mx1);
            float al0 = ex2(m_lo - mn0);
            float al1 = ex2(m_hi - mn1);
            m_lo = mn0;  m_hi = mn1;
#pragma unroll
            for (int nf = 0; nf < 8; nf++) {
                S[nf][0] = ex2(S[nf][0] - mn0);
                S[nf][1] = ex2(S[nf][1] - mn0);
                S[nf][2] = ex2(S[nf][2] - mn1);
                S[nf][3] = ex2(S[nf][3] - mn1);
            }
#pragma unroll
            for (int nf = 0; nf < 9; nf++) {
                O[nf][0] *= al0; O[nf][1] *= al0;
                O[nf][2] *= al1; O[nf][3] *= al1;
            }

            unsigned aP[4][4];
#pragma unroll
            for (int ks = 0; ks < 4; ks++) {
                aP[ks][0] = packh2(S[2 * ks][0],     S[2 * ks][1]);
                aP[ks][1] = packh2(S[2 * ks][2],     S[2 * ks][3]);
                aP[ks][2] = packh2(S[2 * ks + 1][0], S[2 * ks + 1][1]);
                aP[ks][3] = packh2(S[2 * ks + 1][2], S[2 * ks + 1][3]);
            }

#pragma unroll
            for (int nf = 0; nf < 9; nf++) {
                unsigned vf[8];
                ldsm_x4t(vf,     vfc + boff + (unsigned)(nf * 8) * 2);
                ldsm_x4t(vf + 4, vfc + boff + (unsigned)(32 * ATSP + nf * 8) * 2);
#pragma unroll
                for (int ks = 0; ks < 4; ks++)
                    mma_f16(O[nf], aP[ks], vf + ((ks & 1) * 2) + ((ks >> 1) * 4));
            }
        }

        __syncthreads();
        if (kb + 2 < nkb) issue_kv(kb + 2, buf);
    }

    // recover row sums from ones-column (quad lane t=0 holds col 64)
    const int qsrc = lane & 28;
    const float l_lo = __shfl_sync(0xffffffffu, O[8][0], qsrc);
    const float l_hi = __shfl_sync(0xffffffffu, O[8][2], qsrc);

    const float inv0 = 1.0f / l_lo;
    const float inv1 = 1.0f / l_hi;
    const int r0 = rw0 + g;
    const int r1 = r0 + 8;
    __half* yr0 = y + ((size_t)b * TT + r0) * DIMM + h * DHH;
    __half* yr1 = y + ((size_t)b * TT + r1) * DIMM + h * DHH;
#pragma unroll
    for (int nf = 0; nf < 8; nf++) {
        int c = nf * 8 + 2 * t;
        *(unsigned*)&yr0[c] = packh2(O[nf][0] * inv0, O[nf][1] * inv0);
        *(unsigned*)&yr1[c] = packh2(O[nf][2] * inv1, O[nf][3] * inv1);
    }
}

// ---------------------------------------------------------------------------
extern "C" void kernel_launch(void* const* d_in, const int* in_sizes, int n_in,
                              void* d_out, int out_size)
{
    const float* x     = (const float*)d_in[0];
    const float* W_qkv = (const float*)d_in[2];
    const float* b_qkv = (const float*)d_in[3];
    const float* W_out = (const float*)d_in[4];
    const float* b_out = (const float*)d_in[5];
    float* out = (float*)d_out;

    float2* rope;
    __half *qkvh, *y, *xh, *wqkvh, *wouth;
    cudaGetSymbolAddress((void**)&qkvh, g_qkvh);
    cudaGetSymbolAddress((void**)&y, g_y);
    cudaGetSymbolAddress((void**)&xh, g_xh);
    cudaGetSymbolAddress((void**)&wqkvh, g_wqkvh);
    cudaGetSymbolAddress((void**)&wouth, g_wouth);
    cudaGetSymbolAddress((void**)&rope, g_rope);

    const int gemm_smem = 3 * GSTGH * 2;                 // 56832 B
    cudaFuncSetAttribute(gemm_f16_kernel<0>,
                         cudaFuncAttributeMaxDynamicSharedMemorySize, gemm_smem);
    cudaFuncSetAttribute(gemm_f16_kernel<1>,
                         cudaFuncAttributeMaxDynamicSharedMemorySize, gemm_smem);
    const int attn_smem = (128 + 4 * 64) * ATSP * 2;     // 55296 B
    cudaFuncSetAttribute(attn_f16_kernel,
                         cudaFuncAttributeMaxDynamicSharedMemorySize, attn_smem);

    // 0) fp16 conversions + rope table (one launch)
    prologue_kernel<<<(NTOT4 + TT * 32 + 255) / 256, 256>>>(
        x, xh, W_qkv, wqkvh, W_out, wouth, rope);

    // 1) qkvh = rope(xh @ wqkvh + b_qkv), q pre-scaled by 0.125*log2e
    gemm_f16_kernel<1><<<dim3(QKVN / 128, MROWS / 128), 256, gemm_smem>>>(
        xh, wqkvh, b_qkv, nullptr, qkvh, rope, MROWS, QKVN, DIMM);

    // 2) causal flash attention -> y (fp16)
    attn_f16_kernel<<<dim3(TT / 128, HH, BB), 256, attn_smem>>>(qkvh, y);

    // 3) out = y @ wouth + b_out (fp32)
    gemm_f16_kernel<0><<<dim3(DIMM / 128, MROWS / 128), 256, gemm_smem>>>(
        y, wouth, b_out, out, nullptr, nullptr, MROWS, DIMM, DIMM);
}